// round 2
// baseline (speedup 1.0000x reference)
#include <cuda_runtime.h>
#include <cuda_bf16.h>
#include <cstdint>
#include <math.h>

#define N_HALF 2048
#define NTOT   4096
#define D      512
#define TEMP_INV 10.0f   // 1/TEMPERATURE
#define GAMMA    0.5f    // 1/(2*SIGMA^2)

// ---------------- scratch (static device memory; no allocations) ------------
__device__ __nv_bfloat16 g_U[(size_t)NTOT * D];       // normalized U, bf16
__device__ float g_G[(size_t)NTOT * NTOT];            // Gram matrix (64 MB)
__device__ float g_invs[N_HALF];                      // 1 / s2[j']
__device__ int   g_lab[N_HALF];
__device__ float g_pos[N_HALF];
__device__ float g_row[NTOT];                         // per-row loss contribution

// ---------------- K0: decode labels (int32 or int64) + copy pos -------------
__global__ void k_decode(const int* __restrict__ labraw,
                         const float* __restrict__ zpos) {
    int t = threadIdx.x;  // 1024 threads
    // int64 detection: if labels are int64 (LE), every odd 32-bit word is 0.
    int bad = (labraw[2 * t + 1] != 0);
    int any = __syncthreads_or(bad);
    bool is64 = (any == 0);
    for (int idx = t; idx < N_HALF; idx += 1024) {
        g_lab[idx] = is64 ? labraw[2 * idx] : labraw[idx];
        g_pos[idx] = zpos[idx];
    }
}

// ---------------- K1: L2 normalize rows -> bf16 U ---------------------------
__global__ void k_norm(const float* __restrict__ zi,
                       const float* __restrict__ zj) {
    int row = blockIdx.x;           // 0..4095
    const float* src = (row < N_HALF) ? (zi + (size_t)row * D)
                                      : (zj + (size_t)(row - N_HALF) * D);
    int t = threadIdx.x;            // 128
    float v[4]; float ss = 0.f;
    #pragma unroll
    for (int q = 0; q < 4; ++q) { float x = src[t + q * 128]; v[q] = x; ss += x * x; }
    #pragma unroll
    for (int o = 16; o > 0; o >>= 1) ss += __shfl_xor_sync(0xffffffffu, ss, o);
    __shared__ float sred[4];
    if ((t & 31) == 0) sred[t >> 5] = ss;
    __syncthreads();
    float tot = sred[0] + sred[1] + sred[2] + sred[3];
    float rinv = 1.f / fmaxf(sqrtf(tot), 1e-12f);
    #pragma unroll
    for (int q = 0; q < 4; ++q)
        g_U[(size_t)row * D + t + q * 128] = __float2bfloat16(v[q] * rinv);
}

// ---------------- K2: column scales  invs[j'] = 1/(2*S[j'] - 1) -------------
__global__ void k_colscale() {
    int j = blockIdx.x, t = threadIdx.x;  // 2048 blocks x 256
    int lj = g_lab[j]; float pj = g_pos[j];
    float acc = 0.f;
    for (int m = t; m < N_HALF; m += 256) {
        float d = g_pos[m] - pj;
        float k = __expf(-GAMMA * d * d);
        acc += (g_lab[m] == lj) ? k : 0.f;
    }
    #pragma unroll
    for (int o = 16; o > 0; o >>= 1) acc += __shfl_xor_sync(0xffffffffu, acc, o);
    __shared__ float sred[8];
    if ((t & 31) == 0) sred[t >> 5] = acc;
    __syncthreads();
    if (t == 0) {
        float S = 0.f;
        #pragma unroll
        for (int w = 0; w < 8; ++w) S += sred[w];
        g_invs[j] = 1.f / (2.f * S - 1.f);
    }
}

// ---------------- K3: G = U * U^T (bf16 mma.sync, fp32 accum) ---------------
// Block tile 128x128, BK=32, 8 warps (2x4), warp tile 64x32.
// Smem rows padded to 40 bf16 (=20 u32, 80B) -> conflict-free fragment LDS.
__global__ __launch_bounds__(256) void k_gemm() {
    __shared__ uint32_t sA[128 * 20];
    __shared__ uint32_t sB[128 * 20];
    int tid = threadIdx.x;
    int warp = tid >> 5, lane = tid & 31;
    int g = lane >> 2, tq = lane & 3;
    int warpRow = (warp >> 2) * 64;
    int warpCol = (warp & 3) * 32;
    int aBase = blockIdx.y * 128;
    int bBase = blockIdx.x * 128;

    float acc[4][4][4];
    #pragma unroll
    for (int a = 0; a < 4; ++a)
        #pragma unroll
        for (int b = 0; b < 4; ++b)
            #pragma unroll
            for (int c = 0; c < 4; ++c) acc[a][b][c] = 0.f;

    const uint32_t* __restrict__ gu = reinterpret_cast<const uint32_t*>(g_U);
    // U row stride = 512 bf16 = 256 u32

    for (int kt = 0; kt < D; kt += 32) {
        #pragma unroll
        for (int it = 0; it < 2; ++it) {
            int idx = tid + it * 256;          // 0..511
            int row = idx >> 2, ch = idx & 3;  // 4 chunks of 8 bf16 per row
            const uint4* pa = reinterpret_cast<const uint4*>(
                gu + (size_t)(aBase + row) * 256 + (kt >> 1) + ch * 4);
            *reinterpret_cast<uint4*>(&sA[row * 20 + ch * 4]) = *pa;
            const uint4* pb = reinterpret_cast<const uint4*>(
                gu + (size_t)(bBase + row) * 256 + (kt >> 1) + ch * 4);
            *reinterpret_cast<uint4*>(&sB[row * 20 + ch * 4]) = *pb;
        }
        __syncthreads();
        #pragma unroll
        for (int kk = 0; kk < 2; ++kk) {       // two k16 steps per BK=32
            uint32_t af[4][4], bf[4][2];
            #pragma unroll
            for (int mi = 0; mi < 4; ++mi) {
                int base = (warpRow + mi * 16 + g) * 20 + kk * 8 + tq;
                af[mi][0] = sA[base];
                af[mi][1] = sA[base + 8 * 20];
                af[mi][2] = sA[base + 4];
                af[mi][3] = sA[base + 8 * 20 + 4];
            }
            #pragma unroll
            for (int ni = 0; ni < 4; ++ni) {
                int bb = (warpCol + ni * 8 + g) * 20 + kk * 8 + tq;
                bf[ni][0] = sB[bb];
                bf[ni][1] = sB[bb + 4];
            }
            #pragma unroll
            for (int mi = 0; mi < 4; ++mi)
                #pragma unroll
                for (int ni = 0; ni < 4; ++ni) {
                    asm volatile(
                        "mma.sync.aligned.m16n8k16.row.col.f32.bf16.bf16.f32 "
                        "{%0,%1,%2,%3}, {%4,%5,%6,%7}, {%8,%9}, {%0,%1,%2,%3};\n"
                        : "+f"(acc[mi][ni][0]), "+f"(acc[mi][ni][1]),
                          "+f"(acc[mi][ni][2]), "+f"(acc[mi][ni][3])
                        : "r"(af[mi][0]), "r"(af[mi][1]),
                          "r"(af[mi][2]), "r"(af[mi][3]),
                          "r"(bf[ni][0]), "r"(bf[ni][1]));
                }
        }
        __syncthreads();
    }
    // epilogue
    #pragma unroll
    for (int mi = 0; mi < 4; ++mi) {
        int r = aBase + warpRow + mi * 16 + g;
        #pragma unroll
        for (int ni = 0; ni < 4; ++ni) {
            int c = bBase + warpCol + ni * 8 + tq * 2;
            float2 v0 = make_float2(acc[mi][ni][0], acc[mi][ni][1]);
            float2 v1 = make_float2(acc[mi][ni][2], acc[mi][ni][3]);
            *reinterpret_cast<float2*>(&g_G[(size_t)r * NTOT + c]) = v0;
            *reinterpret_cast<float2*>(&g_G[(size_t)(r + 8) * NTOT + c]) = v1;
        }
    }
}

// ---------------- K4: per-row online LSE + weighted sums --------------------
// One block per i' in [0,2048): handles rows i and i+2048 (they share the
// weight vector). Online logsumexp, fully deterministic reduction order.
__global__ __launch_bounds__(256) void k_rows() {
    __shared__ float sw[N_HALF];
    int i = blockIdx.x, t = threadIdx.x;
    int li = g_lab[i]; float pi = g_pos[i];
    for (int j = t; j < N_HALF; j += 256) {
        float d = pi - g_pos[j];
        sw[j] = (g_lab[j] == li) ? __expf(-GAMMA * d * d) * g_invs[j] : 0.f;
    }
    __syncthreads();

    int r0 = i, r1 = i + N_HALF;
    const float* __restrict__ G0 = &g_G[(size_t)r0 * NTOT];
    const float* __restrict__ G1 = &g_G[(size_t)r1 * NTOT];
    float m0 = -1e30f, s0 = 0.f, A0 = 0.f, W0 = 0.f;
    float m1 = -1e30f, s1 = 0.f, A1 = 0.f, W1 = 0.f;

    for (int j = t; j < NTOT; j += 256) {
        float w = sw[j & (N_HALF - 1)];
        float sim0 = G0[j] * TEMP_INV;
        float sim1 = G1[j] * TEMP_INV;
        if (j != r0) {
            if (sim0 > m0) { s0 = s0 * __expf(m0 - sim0) + 1.f; m0 = sim0; }
            else           { s0 += __expf(sim0 - m0); }
            A0 += sim0 * w; W0 += w;
        }
        if (j != r1) {
            if (sim1 > m1) { s1 = s1 * __expf(m1 - sim1) + 1.f; m1 = sim1; }
            else           { s1 += __expf(sim1 - m1); }
            A1 += sim1 * w; W1 += w;
        }
    }
    // warp reduction
    #pragma unroll
    for (int o = 16; o > 0; o >>= 1) {
        float mo, so, M;
        mo = __shfl_xor_sync(0xffffffffu, m0, o);
        so = __shfl_xor_sync(0xffffffffu, s0, o);
        M = fmaxf(m0, mo);
        s0 = s0 * __expf(m0 - M) + so * __expf(mo - M); m0 = M;
        mo = __shfl_xor_sync(0xffffffffu, m1, o);
        so = __shfl_xor_sync(0xffffffffu, s1, o);
        M = fmaxf(m1, mo);
        s1 = s1 * __expf(m1 - M) + so * __expf(mo - M); m1 = M;
        A0 += __shfl_xor_sync(0xffffffffu, A0, o);
        W0 += __shfl_xor_sync(0xffffffffu, W0, o);
        A1 += __shfl_xor_sync(0xffffffffu, A1, o);
        W1 += __shfl_xor_sync(0xffffffffu, W1, o);
    }
    __shared__ float red[8][8];
    if ((t & 31) == 0) {
        int w = t >> 5;
        red[0][w] = m0; red[1][w] = s0; red[2][w] = A0; red[3][w] = W0;
        red[4][w] = m1; red[5][w] = s1; red[6][w] = A1; red[7][w] = W1;
    }
    __syncthreads();
    if (t == 0) {
        float M0 = red[0][0], S0 = red[1][0], a0 = red[2][0], w0 = red[3][0];
        float M1 = red[4][0], S1 = red[5][0], a1 = red[6][0], w1 = red[7][0];
        #pragma unroll
        for (int k = 1; k < 8; ++k) {
            float mo = red[0][k], so = red[1][k];
            float M = fmaxf(M0, mo);
            S0 = S0 * __expf(M0 - M) + so * __expf(mo - M); M0 = M;
            a0 += red[2][k]; w0 += red[3][k];
            mo = red[4][k]; so = red[5][k];
            M = fmaxf(M1, mo);
            S1 = S1 * __expf(M1 - M) + so * __expf(mo - M); M1 = M;
            a1 += red[6][k]; w1 += red[7][k];
        }
        float lse0 = M0 + logf(S0);
        float lse1 = M1 + logf(S1);
        g_row[r0] = a0 - lse0 * w0;
        g_row[r1] = a1 - lse1 * w1;
    }
}

// ---------------- K5: final deterministic reduction -------------------------
__global__ void k_final(float* __restrict__ out) {
    int t = threadIdx.x;  // 1024
    float a = g_row[t] + g_row[t + 1024] + g_row[t + 2048] + g_row[t + 3072];
    #pragma unroll
    for (int o = 16; o > 0; o >>= 1) a += __shfl_xor_sync(0xffffffffu, a, o);
    __shared__ float sred[32];
    if ((t & 31) == 0) sred[t >> 5] = a;
    __syncthreads();
    if (t == 0) {
        float tot = 0.f;
        #pragma unroll
        for (int w = 0; w < 32; ++w) tot += sred[w];
        out[0] = -tot / (float)N_HALF;
    }
}

// ---------------- launch -----------------------------------------------------
extern "C" void kernel_launch(void* const* d_in, const int* in_sizes, int n_in,
                              void* d_out, int out_size) {
    const float* z_i   = (const float*)d_in[0];
    const float* z_j   = (const float*)d_in[1];
    const int*   labs  = (const int*)d_in[2];
    const float* z_pos = (const float*)d_in[3];
    float* out = (float*)d_out;

    k_decode<<<1, 1024>>>(labs, z_pos);
    k_norm<<<NTOT, 128>>>(z_i, z_j);
    k_colscale<<<N_HALF, 256>>>();
    dim3 ggrid(NTOT / 128, NTOT / 128);
    k_gemm<<<ggrid, 256>>>();
    k_rows<<<N_HALF, 256>>>();
    k_final<<<1, 1024>>>(out);
}

// round 4
// speedup vs baseline: 1.8867x; 1.8867x over previous
#include <cuda_runtime.h>
#include <cuda_bf16.h>
#include <cstdint>
#include <math.h>

#define N_HALF 2048
#define NTOT   4096
#define D      512
#define TEMP_INV 10.0f   // 1/TEMPERATURE (also the exact sim upper bound)
#define GAMMA    0.5f    // 1/(2*SIGMA^2)

#define BM 128
#define BN 128
#define BK 64                     // bf16 per stage chunk (128B rows)
#define NCHUNK (D / BK)           // 8 K-chunks

// ---------------- scratch (static device memory; no allocations) ------------
__device__ __nv_bfloat16 g_U[(size_t)NTOT * D];       // normalized U, bf16
__device__ float g_G[(size_t)NTOT * NTOT];            // Gram matrix (64 MB)
__device__ float g_invs[N_HALF];                      // 1 / (2*S[j'] - 1)
__device__ int   g_lab[N_HALF];
__device__ float g_pos[N_HALF];
__device__ float g_row[NTOT];                         // per-row loss contribution

// ---------------- helpers ----------------------------------------------------
__device__ __forceinline__ uint32_t smem_u32(const void* p) {
    uint32_t a;
    asm("{ .reg .u64 t; cvta.to.shared.u64 t, %1; cvt.u32.u64 %0, t; }"
        : "=r"(a) : "l"(p));
    return a;
}
__device__ __forceinline__ void cp16(uint32_t dst, const void* src) {
    asm volatile("cp.async.cg.shared.global [%0], [%1], 16;" :: "r"(dst), "l"(src));
}
#define CP_COMMIT() asm volatile("cp.async.commit_group;" ::: "memory")

__device__ __forceinline__ void ldsm4(uint32_t& r0, uint32_t& r1,
                                      uint32_t& r2, uint32_t& r3, uint32_t addr) {
    asm volatile("ldmatrix.sync.aligned.m8n8.x4.shared.b16 {%0,%1,%2,%3}, [%4];"
                 : "=r"(r0), "=r"(r1), "=r"(r2), "=r"(r3) : "r"(addr));
}
__device__ __forceinline__ void mma16816(float* c, const uint32_t* a,
                                         const uint32_t* b) {
    asm volatile(
        "mma.sync.aligned.m16n8k16.row.col.f32.bf16.bf16.f32 "
        "{%0,%1,%2,%3}, {%4,%5,%6,%7}, {%8,%9}, {%0,%1,%2,%3};\n"
        : "+f"(c[0]), "+f"(c[1]), "+f"(c[2]), "+f"(c[3])
        : "r"(a[0]), "r"(a[1]), "r"(a[2]), "r"(a[3]), "r"(b[0]), "r"(b[1]));
}

// ---------------- K0: decode labels (int32 or int64) + copy pos -------------
__global__ void k_decode(const int* __restrict__ labraw,
                         const float* __restrict__ zpos) {
    int t = threadIdx.x;  // 1024 threads
    int bad = (labraw[2 * t + 1] != 0);
    int any = __syncthreads_or(bad);
    bool is64 = (any == 0);
    for (int idx = t; idx < N_HALF; idx += 1024) {
        g_lab[idx] = is64 ? labraw[2 * idx] : labraw[idx];
        g_pos[idx] = zpos[idx];
    }
}

// ---------------- K1: L2 normalize rows -> bf16 U ---------------------------
__global__ void k_norm(const float* __restrict__ zi,
                       const float* __restrict__ zj) {
    int row = blockIdx.x;           // 0..4095
    const float* src = (row < N_HALF) ? (zi + (size_t)row * D)
                                      : (zj + (size_t)(row - N_HALF) * D);
    int t = threadIdx.x;            // 128
    float v[4]; float ss = 0.f;
    #pragma unroll
    for (int q = 0; q < 4; ++q) { float x = src[t + q * 128]; v[q] = x; ss += x * x; }
    #pragma unroll
    for (int o = 16; o > 0; o >>= 1) ss += __shfl_xor_sync(0xffffffffu, ss, o);
    __shared__ float sred[4];
    if ((t & 31) == 0) sred[t >> 5] = ss;
    __syncthreads();
    float tot = sred[0] + sred[1] + sred[2] + sred[3];
    float rinv = 1.f / fmaxf(sqrtf(tot), 1e-12f);
    #pragma unroll
    for (int q = 0; q < 4; ++q)
        g_U[(size_t)row * D + t + q * 128] = __float2bfloat16(v[q] * rinv);
}

// ---------------- K2: column scales  invs[j'] = 1/(2*S[j'] - 1) -------------
__global__ __launch_bounds__(256) void k_colscale() {
    __shared__ float sp[N_HALF];
    __shared__ int   sl[N_HALF];
    int j = blockIdx.x, t = threadIdx.x;
    for (int m = t; m < N_HALF; m += 256) { sp[m] = g_pos[m]; sl[m] = g_lab[m]; }
    __syncthreads();
    int lj = sl[j]; float pj = sp[j];
    float acc = 0.f;
    for (int m = t; m < N_HALF; m += 256) {
        float d = sp[m] - pj;
        float k = __expf(-GAMMA * d * d);
        acc += (sl[m] == lj) ? k : 0.f;
    }
    #pragma unroll
    for (int o = 16; o > 0; o >>= 1) acc += __shfl_xor_sync(0xffffffffu, acc, o);
    __shared__ float sred[8];
    if ((t & 31) == 0) sred[t >> 5] = acc;
    __syncthreads();
    if (t == 0) {
        float S = 0.f;
        #pragma unroll
        for (int w = 0; w < 8; ++w) S += sred[w];
        g_invs[j] = 1.f / (2.f * S - 1.f);
    }
}

// ---------------- K3: symmetric Gram GEMM (mma.sync + ldmatrix) -------------
// Upper-triangular tiles only (528 CTAs). 256 threads, 8 warps (2x4),
// warp tile 64x32, BK=64, 2-stage cp.async, XOR-swizzled smem.
extern __shared__ uint8_t dynsmem[];

__global__ __launch_bounds__(256, 2) void k_gemm_sym() {
    int tid = threadIdx.x;
    int warp = tid >> 5, lane = tid & 31;
    int g = lane >> 2, tq = lane & 3;
    int warpRow = (warp >> 2) * 64;
    int warpCol = (warp & 3) * 32;

    // triangular decode: blockIdx.x -> (by, bx) with bx >= by
    int b = blockIdx.x, by = 0;
    while (b >= 32 - by) { b -= 32 - by; ++by; }
    int bx = by + b;
    int rowBase = by * BM, colBase = bx * BN;

    uint32_t raw = smem_u32(dynsmem);
    uint32_t base = (raw + 1023u) & ~1023u;
    uint32_t sa[2] = { base,          base + 16384u };
    uint32_t sb[2] = { base + 32768u, base + 49152u };
    float* sT = reinterpret_cast<float*>(dynsmem + (base - raw)); // mirror bounce

    float acc[4][4][4];
    #pragma unroll
    for (int a = 0; a < 4; ++a)
        #pragma unroll
        for (int c = 0; c < 4; ++c)
            #pragma unroll
            for (int k = 0; k < 4; ++k) acc[a][c][k] = 0.f;

    const char* Ub = reinterpret_cast<const char*>(g_U);  // row stride 1024B

    // ldmatrix per-lane address components
    int arow   = (lane & 7) + ((lane >> 3) & 1) * 8;   // row within 16-row frag
    int achsel = lane >> 4;                            // 16B chunk select (k half)
    int brow   = (lane & 7) + ((lane >> 4) << 3);      // n row within 16
    int bchsel = (lane >> 3) & 1;
    int lxor   = lane & 7;

    #define LOAD_TILES(st, ck) do {                                            \
        uint32_t _sa = sa[st], _sb = sb[st];                                   \
        _Pragma("unroll")                                                      \
        for (int _i = 0; _i < 4; ++_i) {                                       \
            int _idx = _i * 256 + tid;                                         \
            int _row = _idx >> 3, _ch = _idx & 7;                              \
            uint32_t _sw = _row * 128 + ((_ch ^ (_row & 7)) << 4);             \
            cp16(_sa + _sw, Ub + (size_t)(rowBase + _row) * 1024 + (ck) * 128 + _ch * 16); \
            cp16(_sb + _sw, Ub + (size_t)(colBase + _row) * 1024 + (ck) * 128 + _ch * 16); \
        }                                                                      \
        CP_COMMIT();                                                           \
    } while (0)

    LOAD_TILES(0, 0);
    LOAD_TILES(1, 1);

    for (int s = 0; s < NCHUNK; ++s) {
        int st = s & 1;
        if (s < NCHUNK - 1) asm volatile("cp.async.wait_group 1;" ::: "memory");
        else                asm volatile("cp.async.wait_group 0;" ::: "memory");
        __syncthreads();

        uint32_t saSt = sa[st], sbSt = sb[st];
        #pragma unroll
        for (int kk = 0; kk < 4; ++kk) {           // 4 x k16 per BK=64
            uint32_t af[4][4], bf[4][2];
            #pragma unroll
            for (int mi = 0; mi < 4; ++mi) {
                uint32_t addr = saSt + (warpRow + mi * 16 + arow) * 128
                              + (((kk * 2 + achsel) ^ lxor) << 4);
                ldsm4(af[mi][0], af[mi][1], af[mi][2], af[mi][3], addr);
            }
            #pragma unroll
            for (int n2 = 0; n2 < 2; ++n2) {
                uint32_t addr = sbSt + (warpCol + n2 * 16 + brow) * 128
                              + (((kk * 2 + bchsel) ^ lxor) << 4);
                uint32_t r0, r1, r2, r3;
                ldsm4(r0, r1, r2, r3, addr);
                bf[n2 * 2][0] = r0;     bf[n2 * 2][1] = r1;
                bf[n2 * 2 + 1][0] = r2; bf[n2 * 2 + 1][1] = r3;
            }
            #pragma unroll
            for (int mi = 0; mi < 4; ++mi)
                #pragma unroll
                for (int ni = 0; ni < 4; ++ni)
                    mma16816(acc[mi][ni], af[mi], bf[ni]);
        }
        __syncthreads();
        if (s + 2 < NCHUNK) LOAD_TILES(st, s + 2);
    }
    #undef LOAD_TILES

    // ---- epilogue 1: direct tile (rowBase, colBase), straight from regs ----
    #pragma unroll
    for (int mi = 0; mi < 4; ++mi) {
        int r = rowBase + warpRow + mi * 16 + g;
        #pragma unroll
        for (int ni = 0; ni < 4; ++ni) {
            int c = colBase + warpCol + ni * 8 + tq * 2;
            *reinterpret_cast<float2*>(&g_G[(size_t)r * NTOT + c]) =
                make_float2(acc[mi][ni][0], acc[mi][ni][1]);
            *reinterpret_cast<float2*>(&g_G[(size_t)(r + 8) * NTOT + c]) =
                make_float2(acc[mi][ni][2], acc[mi][ni][3]);
        }
    }

    // ---- epilogue 2: mirror tile via column-major smem bounce --------------
    if (bx != by) {
        __syncthreads();   // stage buffers now dead for every warp
        #pragma unroll
        for (int mi = 0; mi < 4; ++mi) {
            int r = warpRow + mi * 16 + g;
            #pragma unroll
            for (int ni = 0; ni < 4; ++ni) {
                int c = warpCol + ni * 8 + tq * 2;
                sT[c * 132 + r]           = acc[mi][ni][0];
                sT[(c + 1) * 132 + r]     = acc[mi][ni][1];
                sT[c * 132 + r + 8]       = acc[mi][ni][2];
                sT[(c + 1) * 132 + r + 8] = acc[mi][ni][3];
            }
        }
        __syncthreads();
        #pragma unroll
        for (int it = 0; it < 16; ++it) {
            int idx = it * 256 + tid;        // 4096 float4 groups
            int cc = idx >> 5, q = idx & 31;
            float4 v = *reinterpret_cast<const float4*>(&sT[cc * 132 + q * 4]);
            *reinterpret_cast<float4*>(
                &g_G[(size_t)(colBase + cc) * NTOT + rowBase + q * 4]) = v;
        }
    }
}

// ---------------- K4: per-row fixed-max LSE + weighted sums -----------------
// sim = G*10 with ||u||=1  =>  sim <= 10 (up to bf16 rounding). Fixed max 10:
//   lse = 10 + log(sum exp(sim-10)); diagonal corrected analytically after.
__global__ __launch_bounds__(256) void k_rows() {
    __shared__ float sw[N_HALF];
    __shared__ float red[6][8];
    int i = blockIdx.x, t = threadIdx.x;
    int li = g_lab[i]; float pi = g_pos[i];
    for (int j = t; j < N_HALF; j += 256) {
        float d = pi - g_pos[j];
        sw[j] = (g_lab[j] == li) ? __expf(-GAMMA * d * d) * g_invs[j] : 0.f;
    }
    __syncthreads();

    const float4* __restrict__ G0 =
        reinterpret_cast<const float4*>(&g_G[(size_t)i * NTOT]);
    const float4* __restrict__ G1 =
        reinterpret_cast<const float4*>(&g_G[(size_t)(i + N_HALF) * NTOT]);

    float s0 = 0.f, A0 = 0.f, W0 = 0.f;
    float s1 = 0.f, A1 = 0.f, W1 = 0.f;
    for (int jv = t; jv < NTOT / 4; jv += 256) {
        float4 a = G0[jv], bq = G1[jv];
        int j0 = (jv * 4) & (N_HALF - 1);
        float wA = sw[j0], wB = sw[j0 + 1], wC = sw[j0 + 2], wD_ = sw[j0 + 3];
        float sm;
        sm = a.x * TEMP_INV;  s0 += __expf(sm - TEMP_INV); A0 += sm * wA;  W0 += wA;
        sm = a.y * TEMP_INV;  s0 += __expf(sm - TEMP_INV); A0 += sm * wB;  W0 += wB;
        sm = a.z * TEMP_INV;  s0 += __expf(sm - TEMP_INV); A0 += sm * wC;  W0 += wC;
        sm = a.w * TEMP_INV;  s0 += __expf(sm - TEMP_INV); A0 += sm * wD_; W0 += wD_;
        sm = bq.x * TEMP_INV; s1 += __expf(sm - TEMP_INV); A1 += sm * wA;  W1 += wA;
        sm = bq.y * TEMP_INV; s1 += __expf(sm - TEMP_INV); A1 += sm * wB;  W1 += wB;
        sm = bq.z * TEMP_INV; s1 += __expf(sm - TEMP_INV); A1 += sm * wC;  W1 += wC;
        sm = bq.w * TEMP_INV; s1 += __expf(sm - TEMP_INV); A1 += sm * wD_; W1 += wD_;
    }
    #pragma unroll
    for (int o = 16; o > 0; o >>= 1) {
        s0 += __shfl_xor_sync(0xffffffffu, s0, o);
        A0 += __shfl_xor_sync(0xffffffffu, A0, o);
        W0 += __shfl_xor_sync(0xffffffffu, W0, o);
        s1 += __shfl_xor_sync(0xffffffffu, s1, o);
        A1 += __shfl_xor_sync(0xffffffffu, A1, o);
        W1 += __shfl_xor_sync(0xffffffffu, W1, o);
    }
    if ((t & 31) == 0) {
        int w = t >> 5;
        red[0][w] = s0; red[1][w] = A0; red[2][w] = W0;
        red[3][w] = s1; red[4][w] = A1; red[5][w] = W1;
    }
    __syncthreads();
    if (t == 0) {
        float S0 = 0, a0 = 0, w0 = 0, S1 = 0, a1 = 0, w1 = 0;
        #pragma unroll
        for (int k = 0; k < 8; ++k) {
            S0 += red[0][k]; a0 += red[1][k]; w0 += red[2][k];
            S1 += red[3][k]; a1 += red[4][k]; w1 += red[5][k];
        }
        float swi = sw[i];   // diag weight = invs[i] exactly
        float gd0 = g_G[(size_t)i * NTOT + i] * TEMP_INV;
        float gd1 = g_G[(size_t)(i + N_HALF) * NTOT + (i + N_HALF)] * TEMP_INV;
        S0 -= __expf(gd0 - TEMP_INV); a0 -= gd0 * swi; w0 -= swi;
        S1 -= __expf(gd1 - TEMP_INV); a1 -= gd1 * swi; w1 -= swi;
        float lse0 = TEMP_INV + logf(S0);
        float lse1 = TEMP_INV + logf(S1);
        g_row[i]          = a0 - lse0 * w0;
        g_row[i + N_HALF] = a1 - lse1 * w1;
    }
}

// ---------------- K5: final deterministic reduction -------------------------
__global__ void k_final(float* __restrict__ out) {
    int t = threadIdx.x;  // 1024
    float a = g_row[t] + g_row[t + 1024] + g_row[t + 2048] + g_row[t + 3072];
    #pragma unroll
    for (int o = 16; o > 0; o >>= 1) a += __shfl_xor_sync(0xffffffffu, a, o);
    __shared__ float sred[32];
    if ((t & 31) == 0) sred[t >> 5] = a;
    __syncthreads();
    if (t == 0) {
        float tot = 0.f;
        #pragma unroll
        for (int w = 0; w < 32; ++w) tot += sred[w];
        out[0] = -tot / (float)N_HALF;
    }
}

// ---------------- launch -----------------------------------------------------
extern "C" void kernel_launch(void* const* d_in, const int* in_sizes, int n_in,
                              void* d_out, int out_size) {
    const float* z_i   = (const float*)d_in[0];
    const float* z_j   = (const float*)d_in[1];
    const int*   labs  = (const int*)d_in[2];
    const float* z_pos = (const float*)d_in[3];
    float* out = (float*)d_out;

    const int dyn_smem = 69632;   // max(2x32KB stages, 128x132 f32 bounce) + align
    cudaFuncSetAttribute(k_gemm_sym, cudaFuncAttributeMaxDynamicSharedMemorySize,
                         dyn_smem);

    k_decode<<<1, 1024>>>(labs, z_pos);
    k_norm<<<NTOT, 128>>>(z_i, z_j);
    k_colscale<<<N_HALF, 256>>>();
    k_gemm_sym<<<528, 256, dyn_smem>>>();
    k_rows<<<N_HALF, 256>>>();
    k_final<<<1, 1024>>>(out);
}

// round 5
// speedup vs baseline: 2.1910x; 1.1613x over previous
#include <cuda_runtime.h>
#include <cuda_bf16.h>
#include <cstdint>
#include <math.h>

#define N_HALF 2048
#define NTOT   4096
#define D      512
#define TEMP_INV 10.0f   // 1/TEMPERATURE (also the exact sim upper bound)
#define GAMMA    0.5f    // 1/(2*SIGMA^2)

#define BM 128
#define BN 128
#define BK 64                     // bf16 per stage chunk (128B rows)
#define NCHUNK (D / BK)           // 8 K-chunks

#define FP_SCALE 1099511627776.0  // 2^40 fixed-point scale (deterministic atomics)

// ---------------- scratch (static device memory; no allocations) ------------
__device__ __nv_bfloat16 g_U[(size_t)NTOT * D];       // normalized U, bf16
__device__ float g_invs[N_HALF];                      // 1 / (2*S[j'] - 1)
__device__ int   g_lab[N_HALF];
__device__ float g_pos[N_HALF];
// fixed-point per-row accumulators: S (softmax denom), A (sum sim*w), W (sum w)
__device__ unsigned long long g_accS[NTOT];
__device__ unsigned long long g_accA[NTOT];
__device__ unsigned long long g_accW[NTOT];

// ---------------- helpers ----------------------------------------------------
__device__ __forceinline__ uint32_t smem_u32(const void* p) {
    uint32_t a;
    asm("{ .reg .u64 t; cvta.to.shared.u64 t, %1; cvt.u32.u64 %0, t; }"
        : "=r"(a) : "l"(p));
    return a;
}
__device__ __forceinline__ void cp16(uint32_t dst, const void* src) {
    asm volatile("cp.async.cg.shared.global [%0], [%1], 16;" :: "r"(dst), "l"(src));
}
#define CP_COMMIT() asm volatile("cp.async.commit_group;" ::: "memory")

__device__ __forceinline__ void ldsm4(uint32_t& r0, uint32_t& r1,
                                      uint32_t& r2, uint32_t& r3, uint32_t addr) {
    asm volatile("ldmatrix.sync.aligned.m8n8.x4.shared.b16 {%0,%1,%2,%3}, [%4];"
                 : "=r"(r0), "=r"(r1), "=r"(r2), "=r"(r3) : "r"(addr));
}
__device__ __forceinline__ void mma16816(float* c, const uint32_t* a,
                                         const uint32_t* b) {
    asm volatile(
        "mma.sync.aligned.m16n8k16.row.col.f32.bf16.bf16.f32 "
        "{%0,%1,%2,%3}, {%4,%5,%6,%7}, {%8,%9}, {%0,%1,%2,%3};\n"
        : "+f"(c[0]), "+f"(c[1]), "+f"(c[2]), "+f"(c[3])
        : "r"(a[0]), "r"(a[1]), "r"(a[2]), "r"(a[3]), "r"(b[0]), "r"(b[1]));
}
__device__ __forceinline__ void atomic_add_fx(unsigned long long* p, float v) {
    long long q = (long long)((double)v * FP_SCALE);
    atomicAdd(p, (unsigned long long)q);
}

// ---------------- K0: decode labels + copy pos + zero accumulators ----------
__global__ void k_decode(const int* __restrict__ labraw,
                         const float* __restrict__ zpos) {
    int t = threadIdx.x;  // 1024 threads
    int bad = (labraw[2 * t + 1] != 0);
    int any = __syncthreads_or(bad);
    bool is64 = (any == 0);
    for (int idx = t; idx < N_HALF; idx += 1024) {
        g_lab[idx] = is64 ? labraw[2 * idx] : labraw[idx];
        g_pos[idx] = zpos[idx];
    }
    for (int idx = t; idx < NTOT; idx += 1024) {
        g_accS[idx] = 0ull; g_accA[idx] = 0ull; g_accW[idx] = 0ull;
    }
}

// ---------------- K1: L2 normalize rows -> bf16 U ---------------------------
__global__ void k_norm(const float* __restrict__ zi,
                       const float* __restrict__ zj) {
    int row = blockIdx.x;           // 0..4095
    const float* src = (row < N_HALF) ? (zi + (size_t)row * D)
                                      : (zj + (size_t)(row - N_HALF) * D);
    int t = threadIdx.x;            // 128
    float v[4]; float ss = 0.f;
    #pragma unroll
    for (int q = 0; q < 4; ++q) { float x = src[t + q * 128]; v[q] = x; ss += x * x; }
    #pragma unroll
    for (int o = 16; o > 0; o >>= 1) ss += __shfl_xor_sync(0xffffffffu, ss, o);
    __shared__ float sred[4];
    if ((t & 31) == 0) sred[t >> 5] = ss;
    __syncthreads();
    float tot = sred[0] + sred[1] + sred[2] + sred[3];
    float rinv = 1.f / fmaxf(sqrtf(tot), 1e-12f);
    #pragma unroll
    for (int q = 0; q < 4; ++q)
        g_U[(size_t)row * D + t + q * 128] = __float2bfloat16(v[q] * rinv);
}

// ---------------- K2: column scales  invs[j'] = 1/(2*S[j'] - 1) -------------
__global__ __launch_bounds__(256) void k_colscale() {
    __shared__ float sp[N_HALF];
    __shared__ int   sl[N_HALF];
    int j = blockIdx.x, t = threadIdx.x;
    for (int m = t; m < N_HALF; m += 256) { sp[m] = g_pos[m]; sl[m] = g_lab[m]; }
    __syncthreads();
    int lj = sl[j]; float pj = sp[j];
    float acc = 0.f;
    for (int m = t; m < N_HALF; m += 256) {
        float d = sp[m] - pj;
        float k = __expf(-GAMMA * d * d);
        acc += (sl[m] == lj) ? k : 0.f;
    }
    #pragma unroll
    for (int o = 16; o > 0; o >>= 1) acc += __shfl_xor_sync(0xffffffffu, acc, o);
    __shared__ float sred[8];
    if ((t & 31) == 0) sred[t >> 5] = acc;
    __syncthreads();
    if (t == 0) {
        float S = 0.f;
        #pragma unroll
        for (int w = 0; w < 8; ++w) S += sred[w];
        g_invs[j] = 1.f / (2.f * S - 1.f);
    }
}

// ---------------- K3: fused symmetric Gram GEMM + row statistics ------------
// Upper-triangular tiles (528 CTAs). Mainloop: 256 thr, 8 warps (2x4),
// warp tile 64x32, BK=64, 2-stage cp.async, XOR-swizzled smem, ldmatrix.
// Epilogue: per-element softmax/weight stats for BOTH orientations, reduced
// per-CTA, then fixed-point int64 atomics (deterministic).
extern __shared__ uint8_t dynsmem[];

__global__ __launch_bounds__(256, 2) void k_gemm_fused() {
    int tid = threadIdx.x;
    int warp = tid >> 5, lane = tid & 31;
    int g = lane >> 2, tq = lane & 3;
    int warpRow = (warp >> 2) * 64;
    int warpCol = (warp & 3) * 32;

    // triangular decode: blockIdx.x -> (by, bx) with bx >= by
    int b = blockIdx.x, by = 0;
    while (b >= 32 - by) { b -= 32 - by; ++by; }
    int bx = by + b;
    int rowBase = by * BM, colBase = bx * BN;
    bool diag = (bx == by);

    uint32_t raw = smem_u32(dynsmem);
    uint32_t base = (raw + 1023u) & ~1023u;
    uint32_t sa[2] = { base,          base + 16384u };
    uint32_t sb[2] = { base + 32768u, base + 49152u };
    uint8_t* ep = dynsmem + (base - raw);   // epilogue scratch (reuses stages)
    float* pR_s = reinterpret_cast<float*>(ep);            // [128]
    float* iR_s = pR_s + 128;                              // [128]
    int*   lR_s = reinterpret_cast<int*>(iR_s + 128);      // [128]
    float* pC_s = reinterpret_cast<float*>(lR_s + 128);    // [128]
    float* iC_s = pC_s + 128;                              // [128]
    int*   lC_s = reinterpret_cast<int*>(iC_s + 128);      // [128]
    float* partR = reinterpret_cast<float*>(lC_s + 128);   // [8][64][3]
    float* partC = partR + 8 * 64 * 3;                     // [8][32][3]

    float acc[4][4][4];
    #pragma unroll
    for (int a = 0; a < 4; ++a)
        #pragma unroll
        for (int c = 0; c < 4; ++c)
            #pragma unroll
            for (int k = 0; k < 4; ++k) acc[a][c][k] = 0.f;

    const char* Ub = reinterpret_cast<const char*>(g_U);  // row stride 1024B

    int arow   = (lane & 7) + ((lane >> 3) & 1) * 8;
    int achsel = lane >> 4;
    int brow   = (lane & 7) + ((lane >> 4) << 3);
    int bchsel = (lane >> 3) & 1;
    int lxor   = lane & 7;

    #define LOAD_TILES(st, ck) do {                                            \
        uint32_t _sa = sa[st], _sb = sb[st];                                   \
        _Pragma("unroll")                                                      \
        for (int _i = 0; _i < 4; ++_i) {                                       \
            int _idx = _i * 256 + tid;                                         \
            int _row = _idx >> 3, _ch = _idx & 7;                              \
            uint32_t _sw = _row * 128 + ((_ch ^ (_row & 7)) << 4);             \
            cp16(_sa + _sw, Ub + (size_t)(rowBase + _row) * 1024 + (ck) * 128 + _ch * 16); \
            cp16(_sb + _sw, Ub + (size_t)(colBase + _row) * 1024 + (ck) * 128 + _ch * 16); \
        }                                                                      \
        CP_COMMIT();                                                           \
    } while (0)

    LOAD_TILES(0, 0);
    LOAD_TILES(1, 1);

    for (int s = 0; s < NCHUNK; ++s) {
        int st = s & 1;
        if (s < NCHUNK - 1) asm volatile("cp.async.wait_group 1;" ::: "memory");
        else                asm volatile("cp.async.wait_group 0;" ::: "memory");
        __syncthreads();

        uint32_t saSt = sa[st], sbSt = sb[st];
        #pragma unroll
        for (int kk = 0; kk < 4; ++kk) {
            uint32_t af[4][4], bf[4][2];
            #pragma unroll
            for (int mi = 0; mi < 4; ++mi) {
                uint32_t addr = saSt + (warpRow + mi * 16 + arow) * 128
                              + (((kk * 2 + achsel) ^ lxor) << 4);
                ldsm4(af[mi][0], af[mi][1], af[mi][2], af[mi][3], addr);
            }
            #pragma unroll
            for (int n2 = 0; n2 < 2; ++n2) {
                uint32_t addr = sbSt + (warpCol + n2 * 16 + brow) * 128
                              + (((kk * 2 + bchsel) ^ lxor) << 4);
                uint32_t r0, r1, r2, r3;
                ldsm4(r0, r1, r2, r3, addr);
                bf[n2 * 2][0] = r0;     bf[n2 * 2][1] = r1;
                bf[n2 * 2 + 1][0] = r2; bf[n2 * 2 + 1][1] = r3;
            }
            #pragma unroll
            for (int mi = 0; mi < 4; ++mi)
                #pragma unroll
                for (int ni = 0; ni < 4; ++ni)
                    mma16816(acc[mi][ni], af[mi], bf[ni]);
        }
        __syncthreads();
        if (s + 2 < NCHUNK) LOAD_TILES(st, s + 2);
    }
    #undef LOAD_TILES

    // ================= fused epilogue =================
    // metadata into smem (stage buffers now dead)
    if (tid < 128) {
        int r = (rowBase + tid) & (N_HALF - 1);
        int c = (colBase + tid) & (N_HALF - 1);
        pR_s[tid] = g_pos[r]; iR_s[tid] = g_invs[r]; lR_s[tid] = g_lab[r];
        pC_s[tid] = g_pos[c]; iC_s[tid] = g_invs[c]; lC_s[tid] = g_lab[c];
    }
    __syncthreads();

    float rS[8], rA[8], rW[8], cS[8], cA[8], cW[8];
    #pragma unroll
    for (int i = 0; i < 8; ++i) {
        rS[i] = rA[i] = rW[i] = 0.f;
        cS[i] = cA[i] = cW[i] = 0.f;
    }

    #pragma unroll
    for (int mi = 0; mi < 4; ++mi) {
        #pragma unroll
        for (int kh = 0; kh < 2; ++kh) {
            int rl = warpRow + mi * 16 + kh * 8 + g;
            float pr = pR_s[rl], ir = iR_s[rl];
            int   lr = lR_s[rl];
            int idxR = mi * 2 + kh;
            #pragma unroll
            for (int ni = 0; ni < 4; ++ni) {
                #pragma unroll
                for (int kb = 0; kb < 2; ++kb) {
                    int cl = warpCol + ni * 8 + tq * 2 + kb;
                    float sim = acc[mi][ni][kh * 2 + kb] * TEMP_INV;
                    float eS = __expf(sim - TEMP_INV);
                    float d  = pr - pC_s[cl];
                    float wk = (lr == lC_s[cl]) ? __expf(-GAMMA * d * d) : 0.f;
                    if (diag && rl == cl) { eS = 0.f; wk = 0.f; }
                    float wc = wk * iC_s[cl];
                    int idxC = ni * 2 + kb;
                    rS[idxR] += eS; rA[idxR] += sim * wc; rW[idxR] += wc;
                    float wr = wk * ir;
                    cS[idxC] += eS; cA[idxC] += sim * wr; cW[idxC] += wr;
                }
            }
        }
    }

    // warp reductions: rows over tq (xor 1,2); cols over g (xor 4,8,16)
    #pragma unroll
    for (int i = 0; i < 8; ++i) {
        rS[i] += __shfl_xor_sync(0xffffffffu, rS[i], 1);
        rS[i] += __shfl_xor_sync(0xffffffffu, rS[i], 2);
        rA[i] += __shfl_xor_sync(0xffffffffu, rA[i], 1);
        rA[i] += __shfl_xor_sync(0xffffffffu, rA[i], 2);
        rW[i] += __shfl_xor_sync(0xffffffffu, rW[i], 1);
        rW[i] += __shfl_xor_sync(0xffffffffu, rW[i], 2);
        cS[i] += __shfl_xor_sync(0xffffffffu, cS[i], 4);
        cS[i] += __shfl_xor_sync(0xffffffffu, cS[i], 8);
        cS[i] += __shfl_xor_sync(0xffffffffu, cS[i], 16);
        cA[i] += __shfl_xor_sync(0xffffffffu, cA[i], 4);
        cA[i] += __shfl_xor_sync(0xffffffffu, cA[i], 8);
        cA[i] += __shfl_xor_sync(0xffffffffu, cA[i], 16);
        cW[i] += __shfl_xor_sync(0xffffffffu, cW[i], 4);
        cW[i] += __shfl_xor_sync(0xffffffffu, cW[i], 8);
        cW[i] += __shfl_xor_sync(0xffffffffu, cW[i], 16);
    }
    if (tq == 0) {
        #pragma unroll
        for (int i = 0; i < 8; ++i) {
            int rl = (i >> 1) * 16 + (i & 1) * 8 + g;   // 0..63 within warp
            float* p = &partR[(warp * 64 + rl) * 3];
            p[0] = rS[i]; p[1] = rA[i]; p[2] = rW[i];
        }
    }
    if (g == 0) {
        #pragma unroll
        for (int i = 0; i < 8; ++i) {
            int cl = (i >> 1) * 8 + tq * 2 + (i & 1);   // 0..31 within warp
            float* p = &partC[(warp * 32 + cl) * 3];
            p[0] = cS[i]; p[1] = cA[i]; p[2] = cW[i];
        }
    }
    __syncthreads();

    // CTA-level sums + deterministic fixed-point atomics
    if (tid < 128) {
        int wb = (tid >> 6) * 4;      // rows 0-63 <- warps 0-3; 64-127 <- 4-7
        int lr2 = tid & 63;
        float S = 0.f, A = 0.f, W = 0.f;
        #pragma unroll
        for (int w = 0; w < 4; ++w) {
            const float* p = &partR[((wb + w) * 64 + lr2) * 3];
            S += p[0]; A += p[1]; W += p[2];
        }
        int grow = rowBase + tid;
        atomic_add_fx(&g_accS[grow], S);
        atomic_add_fx(&g_accA[grow], A);
        atomic_add_fx(&g_accW[grow], W);
        if (!diag) {
            int grp = tid >> 5, lc2 = tid & 31;
            const float* p0 = &partC[(grp * 32 + lc2) * 3];
            const float* p1 = &partC[((grp + 4) * 32 + lc2) * 3];
            float Sc = p0[0] + p1[0];
            float Ac = p0[1] + p1[1];
            float Wc = p0[2] + p1[2];
            int gcol = colBase + tid;
            atomic_add_fx(&g_accS[gcol], Sc);
            atomic_add_fx(&g_accA[gcol], Ac);
            atomic_add_fx(&g_accW[gcol], Wc);
        }
    }
}

// ---------------- K4: final per-row loss + deterministic reduction ----------
__global__ void k_final(float* __restrict__ out) {
    int t = threadIdx.x;  // 1024
    const double inv_scale = 1.0 / FP_SCALE;
    float a = 0.f;
    #pragma unroll
    for (int q = 0; q < 4; ++q) {
        int r = t + q * 1024;
        double S = (double)(long long)g_accS[r] * inv_scale;
        double A = (double)(long long)g_accA[r] * inv_scale;
        double W = (double)(long long)g_accW[r] * inv_scale;
        double lse = (double)TEMP_INV + log(S);
        a += (float)(A - lse * W);
    }
    #pragma unroll
    for (int o = 16; o > 0; o >>= 1) a += __shfl_xor_sync(0xffffffffu, a, o);
    __shared__ float sred[32];
    if ((t & 31) == 0) sred[t >> 5] = a;
    __syncthreads();
    if (t == 0) {
        float tot = 0.f;
        #pragma unroll
        for (int w = 0; w < 32; ++w) tot += sred[w];
        out[0] = -tot / (float)N_HALF;
    }
}

// ---------------- launch -----------------------------------------------------
extern "C" void kernel_launch(void* const* d_in, const int* in_sizes, int n_in,
                              void* d_out, int out_size) {
    const float* z_i   = (const float*)d_in[0];
    const float* z_j   = (const float*)d_in[1];
    const int*   labs  = (const int*)d_in[2];
    const float* z_pos = (const float*)d_in[3];
    float* out = (float*)d_out;

    const int dyn_smem = 66560;   // 2x32KB stages + 1KB alignment slack
    cudaFuncSetAttribute(k_gemm_fused, cudaFuncAttributeMaxDynamicSharedMemorySize,
                         dyn_smem);

    k_decode<<<1, 1024>>>(labs, z_pos);
    k_norm<<<NTOT, 128>>>(z_i, z_j);
    k_colscale<<<N_HALF, 256>>>();
    k_gemm_fused<<<528, 256, dyn_smem>>>();
    k_final<<<1, 1024>>>(out);
}

// round 6
// speedup vs baseline: 2.2373x; 1.0211x over previous
#include <cuda_runtime.h>
#include <cuda_bf16.h>
#include <cstdint>
#include <math.h>

#define N_HALF 2048
#define NTOT   4096
#define D      512
#define TEMP_INV 10.0f   // 1/TEMPERATURE (also the exact sim upper bound)
#define GAMMA    0.5f    // 1/(2*SIGMA^2)

#define BM 128
#define BN 128
#define BK 64                     // bf16 per stage chunk (128B rows)
#define NCHUNK (D / BK)           // 8 K-chunks
#define NSTAGE 3

#define FP_SCALE 1099511627776.0  // 2^40 fixed-point scale (deterministic atomics)

// ---------------- scratch (static device memory; no allocations) ------------
__device__ __nv_bfloat16 g_U[(size_t)NTOT * D];       // normalized U, bf16
__device__ float g_invs[N_HALF];                      // 1 / (2*S[j'] - 1)
__device__ int   g_lab[N_HALF];
__device__ float g_pos[N_HALF];
// fixed-point per-row accumulators: S (softmax denom), A (sum sim*w), W (sum w)
__device__ unsigned long long g_accS[NTOT];
__device__ unsigned long long g_accA[NTOT];
__device__ unsigned long long g_accW[NTOT];

// ---------------- helpers ----------------------------------------------------
__device__ __forceinline__ uint32_t smem_u32(const void* p) {
    uint32_t a;
    asm("{ .reg .u64 t; cvta.to.shared.u64 t, %1; cvt.u32.u64 %0, t; }"
        : "=r"(a) : "l"(p));
    return a;
}
__device__ __forceinline__ void cp16(uint32_t dst, const void* src) {
    asm volatile("cp.async.cg.shared.global [%0], [%1], 16;" :: "r"(dst), "l"(src));
}
#define CP_COMMIT() asm volatile("cp.async.commit_group;" ::: "memory")

__device__ __forceinline__ void ldsm4(uint32_t& r0, uint32_t& r1,
                                      uint32_t& r2, uint32_t& r3, uint32_t addr) {
    asm volatile("ldmatrix.sync.aligned.m8n8.x4.shared.b16 {%0,%1,%2,%3}, [%4];"
                 : "=r"(r0), "=r"(r1), "=r"(r2), "=r"(r3) : "r"(addr));
}
__device__ __forceinline__ void mma16816(float* c, const uint32_t* a,
                                         const uint32_t* b) {
    asm volatile(
        "mma.sync.aligned.m16n8k16.row.col.f32.bf16.bf16.f32 "
        "{%0,%1,%2,%3}, {%4,%5,%6,%7}, {%8,%9}, {%0,%1,%2,%3};\n"
        : "+f"(c[0]), "+f"(c[1]), "+f"(c[2]), "+f"(c[3])
        : "r"(a[0]), "r"(a[1]), "r"(a[2]), "r"(a[3]), "r"(b[0]), "r"(b[1]));
}
__device__ __forceinline__ void atomic_add_fx(unsigned long long* p, float v) {
    long long q = (long long)((double)v * FP_SCALE);
    atomicAdd(p, (unsigned long long)q);
}

// ---------------- K1: L2 normalize rows -> bf16 U ---------------------------
__global__ void k_norm(const float* __restrict__ zi,
                       const float* __restrict__ zj) {
    int row = blockIdx.x;           // 0..4095
    const float* src = (row < N_HALF) ? (zi + (size_t)row * D)
                                      : (zj + (size_t)(row - N_HALF) * D);
    int t = threadIdx.x;            // 128
    float v[4]; float ss = 0.f;
    #pragma unroll
    for (int q = 0; q < 4; ++q) { float x = src[t + q * 128]; v[q] = x; ss += x * x; }
    #pragma unroll
    for (int o = 16; o > 0; o >>= 1) ss += __shfl_xor_sync(0xffffffffu, ss, o);
    __shared__ float sred[4];
    if ((t & 31) == 0) sred[t >> 5] = ss;
    __syncthreads();
    float tot = sred[0] + sred[1] + sred[2] + sred[3];
    float rinv = 1.f / fmaxf(sqrtf(tot), 1e-12f);
    #pragma unroll
    for (int q = 0; q < 4; ++q)
        g_U[(size_t)row * D + t + q * 128] = __float2bfloat16(v[q] * rinv);
}

// ---------------- K2: decode labels + colscale + zero accumulators ----------
// Each block self-decodes labels (int32/int64) into smem, computes
// invs[j] = 1/(2*S[j]-1), publishes lab/pos once (block j writes entry j),
// and zeroes its two accumulator rows.
__global__ __launch_bounds__(256) void k_colscale(const int* __restrict__ labraw,
                                                  const float* __restrict__ zpos) {
    __shared__ float sp[N_HALF];
    __shared__ int   sl[N_HALF];
    __shared__ int   s_is64;
    int j = blockIdx.x, t = threadIdx.x;
    if (t == 0) s_is64 = 1;
    __syncthreads();
    // int64 detection: any nonzero odd word => int32
    for (int m = t; m < N_HALF; m += 256)
        if (labraw[2 * m + 1] != 0) s_is64 = 0;
    for (int m = t; m < N_HALF; m += 256) sp[m] = zpos[m];
    __syncthreads();
    int is64 = s_is64;
    for (int m = t; m < N_HALF; m += 256)
        sl[m] = is64 ? labraw[2 * m] : labraw[m];
    __syncthreads();

    int lj = sl[j]; float pj = sp[j];
    float acc = 0.f;
    for (int m = t; m < N_HALF; m += 256) {
        float d = sp[m] - pj;
        float k = __expf(-GAMMA * d * d);
        acc += (sl[m] == lj) ? k : 0.f;
    }
    #pragma unroll
    for (int o = 16; o > 0; o >>= 1) acc += __shfl_xor_sync(0xffffffffu, acc, o);
    __shared__ float sred[8];
    if ((t & 31) == 0) sred[t >> 5] = acc;
    __syncthreads();
    if (t == 0) {
        float S = 0.f;
        #pragma unroll
        for (int w = 0; w < 8; ++w) S += sred[w];
        g_invs[j] = 1.f / (2.f * S - 1.f);
        g_lab[j] = lj; g_pos[j] = pj;
        g_accS[j] = 0ull; g_accA[j] = 0ull; g_accW[j] = 0ull;
        g_accS[j + N_HALF] = 0ull; g_accA[j + N_HALF] = 0ull;
        g_accW[j + N_HALF] = 0ull;
    }
}

// ---------------- K3: fused symmetric Gram GEMM + row statistics ------------
// Upper-triangular tiles (528 CTAs). Mainloop: 256 thr, 8 warps (2x4),
// warp tile 64x32, BK=64, 3-stage cp.async pipeline (loads for s+2 issued
// BEFORE compute of s), XOR-swizzled smem, ldmatrix. Fused stats epilogue.
extern __shared__ uint8_t dynsmem[];

__global__ __launch_bounds__(256, 2) void k_gemm_fused() {
    int tid = threadIdx.x;
    int warp = tid >> 5, lane = tid & 31;
    int g = lane >> 2, tq = lane & 3;
    int warpRow = (warp >> 2) * 64;
    int warpCol = (warp & 3) * 32;

    // triangular decode: blockIdx.x -> (by, bx) with bx >= by
    int b = blockIdx.x, by = 0;
    while (b >= 32 - by) { b -= 32 - by; ++by; }
    int bx = by + b;
    int rowBase = by * BM, colBase = bx * BN;
    bool diag = (bx == by);

    uint32_t raw = smem_u32(dynsmem);
    uint32_t base = (raw + 1023u) & ~1023u;
    uint32_t sa[NSTAGE], sb[NSTAGE];
    #pragma unroll
    for (int s = 0; s < NSTAGE; ++s) {
        sa[s] = base + s * 16384u;
        sb[s] = base + (NSTAGE + s) * 16384u;
    }
    uint8_t* ep = dynsmem + (base - raw);   // epilogue scratch (reuses stages)
    float* pR_s = reinterpret_cast<float*>(ep);            // [128]
    float* iR_s = pR_s + 128;                              // [128]
    int*   lR_s = reinterpret_cast<int*>(iR_s + 128);      // [128]
    float* pC_s = reinterpret_cast<float*>(lR_s + 128);    // [128]
    float* iC_s = pC_s + 128;                              // [128]
    int*   lC_s = reinterpret_cast<int*>(iC_s + 128);      // [128]
    float* partR = reinterpret_cast<float*>(lC_s + 128);   // [8][64][3]
    float* partC = partR + 8 * 64 * 3;                     // [8][32][3]

    float acc[4][4][4];
    #pragma unroll
    for (int a = 0; a < 4; ++a)
        #pragma unroll
        for (int c = 0; c < 4; ++c)
            #pragma unroll
            for (int k = 0; k < 4; ++k) acc[a][c][k] = 0.f;

    const char* Ub = reinterpret_cast<const char*>(g_U);  // row stride 1024B

    int arow   = (lane & 7) + ((lane >> 3) & 1) * 8;
    int achsel = lane >> 4;
    int brow   = (lane & 7) + ((lane >> 4) << 3);
    int bchsel = (lane >> 3) & 1;
    int lxor   = lane & 7;

    #define LOAD_TILES(st, ck) do {                                            \
        uint32_t _sa = sa[st], _sb = sb[st];                                   \
        _Pragma("unroll")                                                      \
        for (int _i = 0; _i < 4; ++_i) {                                       \
            int _idx = _i * 256 + tid;                                         \
            int _row = _idx >> 3, _ch = _idx & 7;                              \
            uint32_t _sw = _row * 128 + ((_ch ^ (_row & 7)) << 4);             \
            cp16(_sa + _sw, Ub + (size_t)(rowBase + _row) * 1024 + (ck) * 128 + _ch * 16); \
            cp16(_sb + _sw, Ub + (size_t)(colBase + _row) * 1024 + (ck) * 128 + _ch * 16); \
        }                                                                      \
        CP_COMMIT();                                                           \
    } while (0)

    LOAD_TILES(0, 0);
    LOAD_TILES(1, 1);

    #pragma unroll 1
    for (int s = 0; s < NCHUNK; ++s) {
        int st = s % NSTAGE;
        if (s < NCHUNK - 1) asm volatile("cp.async.wait_group 1;" ::: "memory");
        else                asm volatile("cp.async.wait_group 0;" ::: "memory");
        __syncthreads();
        // issue loads for s+2 into the buffer stage (s-1) vacated last iter
        if (s + 2 < NCHUNK) {
            int st2 = (s + 2) % NSTAGE;
            LOAD_TILES(st2, s + 2);
        }

        uint32_t saSt = sa[st], sbSt = sb[st];
        #pragma unroll
        for (int kk = 0; kk < 4; ++kk) {
            uint32_t af[4][4], bf[4][2];
            #pragma unroll
            for (int mi = 0; mi < 4; ++mi) {
                uint32_t addr = saSt + (warpRow + mi * 16 + arow) * 128
                              + (((kk * 2 + achsel) ^ lxor) << 4);
                ldsm4(af[mi][0], af[mi][1], af[mi][2], af[mi][3], addr);
            }
            #pragma unroll
            for (int n2 = 0; n2 < 2; ++n2) {
                uint32_t addr = sbSt + (warpCol + n2 * 16 + brow) * 128
                              + (((kk * 2 + bchsel) ^ lxor) << 4);
                uint32_t r0, r1, r2, r3;
                ldsm4(r0, r1, r2, r3, addr);
                bf[n2 * 2][0] = r0;     bf[n2 * 2][1] = r1;
                bf[n2 * 2 + 1][0] = r2; bf[n2 * 2 + 1][1] = r3;
            }
            #pragma unroll
            for (int mi = 0; mi < 4; ++mi)
                #pragma unroll
                for (int ni = 0; ni < 4; ++ni)
                    mma16816(acc[mi][ni], af[mi], bf[ni]);
        }
    }
    #undef LOAD_TILES

    __syncthreads();   // all compute done; stage buffers reusable

    // ================= fused epilogue =================
    if (tid < 128) {
        int r = (rowBase + tid) & (N_HALF - 1);
        int c = (colBase + tid) & (N_HALF - 1);
        pR_s[tid] = g_pos[r]; iR_s[tid] = g_invs[r]; lR_s[tid] = g_lab[r];
        pC_s[tid] = g_pos[c]; iC_s[tid] = g_invs[c]; lC_s[tid] = g_lab[c];
    }
    __syncthreads();

    float rS[8], rA[8], rW[8], cS[8], cA[8], cW[8];
    #pragma unroll
    for (int i = 0; i < 8; ++i) {
        rS[i] = rA[i] = rW[i] = 0.f;
        cS[i] = cA[i] = cW[i] = 0.f;
    }

    #pragma unroll
    for (int mi = 0; mi < 4; ++mi) {
        #pragma unroll
        for (int kh = 0; kh < 2; ++kh) {
            int rl = warpRow + mi * 16 + kh * 8 + g;
            float pr = pR_s[rl], ir = iR_s[rl];
            int   lr = lR_s[rl];
            int idxR = mi * 2 + kh;
            #pragma unroll
            for (int ni = 0; ni < 4; ++ni) {
                #pragma unroll
                for (int kb = 0; kb < 2; ++kb) {
                    int cl = warpCol + ni * 8 + tq * 2 + kb;
                    float sim = acc[mi][ni][kh * 2 + kb] * TEMP_INV;
                    float eS = __expf(sim - TEMP_INV);
                    float d  = pr - pC_s[cl];
                    float wk = (lr == lC_s[cl]) ? __expf(-GAMMA * d * d) : 0.f;
                    if (diag && rl == cl) { eS = 0.f; wk = 0.f; }
                    float wc = wk * iC_s[cl];
                    int idxC = ni * 2 + kb;
                    rS[idxR] += eS; rA[idxR] += sim * wc; rW[idxR] += wc;
                    float wr = wk * ir;
                    cS[idxC] += eS; cA[idxC] += sim * wr; cW[idxC] += wr;
                }
            }
        }
    }

    // warp reductions: rows over tq (xor 1,2); cols over g (xor 4,8,16)
    #pragma unroll
    for (int i = 0; i < 8; ++i) {
        rS[i] += __shfl_xor_sync(0xffffffffu, rS[i], 1);
        rS[i] += __shfl_xor_sync(0xffffffffu, rS[i], 2);
        rA[i] += __shfl_xor_sync(0xffffffffu, rA[i], 1);
        rA[i] += __shfl_xor_sync(0xffffffffu, rA[i], 2);
        rW[i] += __shfl_xor_sync(0xffffffffu, rW[i], 1);
        rW[i] += __shfl_xor_sync(0xffffffffu, rW[i], 2);
        cS[i] += __shfl_xor_sync(0xffffffffu, cS[i], 4);
        cS[i] += __shfl_xor_sync(0xffffffffu, cS[i], 8);
        cS[i] += __shfl_xor_sync(0xffffffffu, cS[i], 16);
        cA[i] += __shfl_xor_sync(0xffffffffu, cA[i], 4);
        cA[i] += __shfl_xor_sync(0xffffffffu, cA[i], 8);
        cA[i] += __shfl_xor_sync(0xffffffffu, cA[i], 16);
        cW[i] += __shfl_xor_sync(0xffffffffu, cW[i], 4);
        cW[i] += __shfl_xor_sync(0xffffffffu, cW[i], 8);
        cW[i] += __shfl_xor_sync(0xffffffffu, cW[i], 16);
    }
    if (tq == 0) {
        #pragma unroll
        for (int i = 0; i < 8; ++i) {
            int rl = (i >> 1) * 16 + (i & 1) * 8 + g;   // 0..63 within warp
            float* p = &partR[(warp * 64 + rl) * 3];
            p[0] = rS[i]; p[1] = rA[i]; p[2] = rW[i];
        }
    }
    if (g == 0) {
        #pragma unroll
        for (int i = 0; i < 8; ++i) {
            int cl = (i >> 1) * 8 + tq * 2 + (i & 1);   // 0..31 within warp
            float* p = &partC[(warp * 32 + cl) * 3];
            p[0] = cS[i]; p[1] = cA[i]; p[2] = cW[i];
        }
    }
    __syncthreads();

    // CTA-level sums + deterministic fixed-point atomics
    if (tid < 128) {
        int wb = (tid >> 6) * 4;      // rows 0-63 <- warps 0-3; 64-127 <- 4-7
        int lr2 = tid & 63;
        float S = 0.f, A = 0.f, W = 0.f;
        #pragma unroll
        for (int w = 0; w < 4; ++w) {
            const float* p = &partR[((wb + w) * 64 + lr2) * 3];
            S += p[0]; A += p[1]; W += p[2];
        }
        int grow = rowBase + tid;
        atomic_add_fx(&g_accS[grow], S);
        atomic_add_fx(&g_accA[grow], A);
        atomic_add_fx(&g_accW[grow], W);
        if (!diag) {
            int grp = tid >> 5, lc2 = tid & 31;
            const float* p0 = &partC[(grp * 32 + lc2) * 3];
            const float* p1 = &partC[((grp + 4) * 32 + lc2) * 3];
            float Sc = p0[0] + p1[0];
            float Ac = p0[1] + p1[1];
            float Wc = p0[2] + p1[2];
            int gcol = colBase + tid;
            atomic_add_fx(&g_accS[gcol], Sc);
            atomic_add_fx(&g_accA[gcol], Ac);
            atomic_add_fx(&g_accW[gcol], Wc);
        }
    }
}

// ---------------- K4: final per-row loss + deterministic reduction ----------
__global__ void k_final(float* __restrict__ out) {
    int t = threadIdx.x;  // 1024
    const double inv_scale = 1.0 / FP_SCALE;
    float a = 0.f;
    #pragma unroll
    for (int q = 0; q < 4; ++q) {
        int r = t + q * 1024;
        double S = (double)(long long)g_accS[r] * inv_scale;
        double A = (double)(long long)g_accA[r] * inv_scale;
        double W = (double)(long long)g_accW[r] * inv_scale;
        double lse = (double)TEMP_INV + log(S);
        a += (float)(A - lse * W);
    }
    #pragma unroll
    for (int o = 16; o > 0; o >>= 1) a += __shfl_xor_sync(0xffffffffu, a, o);
    __shared__ float sred[32];
    if ((t & 31) == 0) sred[t >> 5] = a;
    __syncthreads();
    if (t == 0) {
        float tot = 0.f;
        #pragma unroll
        for (int w = 0; w < 32; ++w) tot += sred[w];
        out[0] = -tot / (float)N_HALF;
    }
}

// ---------------- launch -----------------------------------------------------
extern "C" void kernel_launch(void* const* d_in, const int* in_sizes, int n_in,
                              void* d_out, int out_size) {
    const float* z_i   = (const float*)d_in[0];
    const float* z_j   = (const float*)d_in[1];
    const int*   labs  = (const int*)d_in[2];
    const float* z_pos = (const float*)d_in[3];
    float* out = (float*)d_out;

    const int dyn_smem = 99328;   // 6 x 16KB stage buffers + 1KB align slack
    cudaFuncSetAttribute(k_gemm_fused, cudaFuncAttributeMaxDynamicSharedMemorySize,
                         dyn_smem);

    k_norm<<<NTOT, 128>>>(z_i, z_j);
    k_colscale<<<N_HALF, 256>>>(labs, z_pos);
    k_gemm_fused<<<528, 256, dyn_smem>>>();
    k_final<<<1, 1024>>>(out);
}

// round 7
// speedup vs baseline: 2.5983x; 1.1614x over previous
#include <cuda_runtime.h>
#include <cuda_bf16.h>
#include <cstdint>
#include <math.h>

#define N_HALF 2048
#define NTOT   4096
#define D      512
#define TEMP_INV 10.0f   // 1/TEMPERATURE (also the exact sim upper bound)
#define GAMMA    0.5f    // 1/(2*SIGMA^2)

#define BM 128
#define BN 128
#define BK 64                     // bf16 per stage chunk (128B rows)
#define NCHUNK (D / BK)           // 8 K-chunks
#define NSTAGE 3

#define FP_SCALE 1099511627776.0  // 2^40 fixed-point scale (deterministic atomics)

// ---------------- scratch (static device memory; no allocations) ------------
__device__ __nv_bfloat16 g_U[(size_t)NTOT * D];       // normalized U, bf16
__device__ float g_invs[N_HALF];                      // 1 / (2*S[j'] - 1)
__device__ int   g_lab[N_HALF];
__device__ float g_pos[N_HALF];
// fixed-point per-row accumulators: S (softmax denom), A (sum sim*w), W (sum w)
__device__ unsigned long long g_accS[NTOT];
__device__ unsigned long long g_accA[NTOT];
__device__ unsigned long long g_accW[NTOT];

// ---------------- helpers ----------------------------------------------------
__device__ __forceinline__ uint32_t smem_u32(const void* p) {
    uint32_t a;
    asm("{ .reg .u64 t; cvta.to.shared.u64 t, %1; cvt.u32.u64 %0, t; }"
        : "=r"(a) : "l"(p));
    return a;
}
__device__ __forceinline__ void cp16(uint32_t dst, const void* src) {
    asm volatile("cp.async.cg.shared.global [%0], [%1], 16;" :: "r"(dst), "l"(src));
}
#define CP_COMMIT() asm volatile("cp.async.commit_group;" ::: "memory")

__device__ __forceinline__ void ldsm4(uint32_t& r0, uint32_t& r1,
                                      uint32_t& r2, uint32_t& r3, uint32_t addr) {
    asm volatile("ldmatrix.sync.aligned.m8n8.x4.shared.b16 {%0,%1,%2,%3}, [%4];"
                 : "=r"(r0), "=r"(r1), "=r"(r2), "=r"(r3) : "r"(addr));
}
__device__ __forceinline__ void mma16816(float* c, const uint32_t* a,
                                         const uint32_t* b) {
    asm volatile(
        "mma.sync.aligned.m16n8k16.row.col.f32.bf16.bf16.f32 "
        "{%0,%1,%2,%3}, {%4,%5,%6,%7}, {%8,%9}, {%0,%1,%2,%3};\n"
        : "+f"(c[0]), "+f"(c[1]), "+f"(c[2]), "+f"(c[3])
        : "r"(a[0]), "r"(a[1]), "r"(a[2]), "r"(a[3]), "r"(b[0]), "r"(b[1]));
}
__device__ __forceinline__ void atomic_add_fx(unsigned long long* p, float v) {
    long long q = (long long)((double)v * FP_SCALE);
    atomicAdd(p, (unsigned long long)q);
}

// ---------------- K1: L2 normalize rows -> bf16 U ---------------------------
__global__ void k_norm(const float* __restrict__ zi,
                       const float* __restrict__ zj) {
    int row = blockIdx.x;           // 0..4095
    const float* src = (row < N_HALF) ? (zi + (size_t)row * D)
                                      : (zj + (size_t)(row - N_HALF) * D);
    int t = threadIdx.x;            // 128
    float v[4]; float ss = 0.f;
    #pragma unroll
    for (int q = 0; q < 4; ++q) { float x = src[t + q * 128]; v[q] = x; ss += x * x; }
    #pragma unroll
    for (int o = 16; o > 0; o >>= 1) ss += __shfl_xor_sync(0xffffffffu, ss, o);
    __shared__ float sred[4];
    if ((t & 31) == 0) sred[t >> 5] = ss;
    __syncthreads();
    float tot = sred[0] + sred[1] + sred[2] + sred[3];
    float rinv = 1.f / fmaxf(sqrtf(tot), 1e-12f);
    #pragma unroll
    for (int q = 0; q < 4; ++q)
        g_U[(size_t)row * D + t + q * 128] = __float2bfloat16(v[q] * rinv);
}

// ---------------- K2: decode + colscale (16 j per block) + zero accs --------
// 128 blocks x 256 threads. Block decodes labels/pos into smem ONCE; each of
// its 8 warps owns 2 j-values and reduces warp-locally (no block syncs in the
// per-j loop). Also zeroes this block's 32 accumulator rows and publishes
// lab/pos for its 16 j's.
__global__ __launch_bounds__(256) void k_colscale(const int* __restrict__ labraw,
                                                  const float* __restrict__ zpos) {
    __shared__ float sp[N_HALF];
    __shared__ int   sl[N_HALF];
    __shared__ int   s_is64;
    int t = threadIdx.x, bb = blockIdx.x;
    int warp = t >> 5, lane = t & 31;
    if (t == 0) s_is64 = 1;
    __syncthreads();
    for (int m = t; m < N_HALF; m += 256)
        if (labraw[2 * m + 1] != 0) s_is64 = 0;
    for (int m = t; m < N_HALF; m += 256) sp[m] = zpos[m];
    __syncthreads();
    int is64 = s_is64;
    for (int m = t; m < N_HALF; m += 256)
        sl[m] = is64 ? labraw[2 * m] : labraw[m];
    __syncthreads();

    #pragma unroll
    for (int q = 0; q < 2; ++q) {
        int j = bb * 16 + warp * 2 + q;
        int lj = sl[j]; float pj = sp[j];
        float acc = 0.f;
        for (int m = lane; m < N_HALF; m += 32) {
            float d = sp[m] - pj;
            float k = __expf(-GAMMA * d * d);
            acc += (sl[m] == lj) ? k : 0.f;
        }
        #pragma unroll
        for (int o = 16; o > 0; o >>= 1)
            acc += __shfl_xor_sync(0xffffffffu, acc, o);
        if (lane == 0) {
            g_invs[j] = 1.f / (2.f * acc - 1.f);
            g_lab[j] = lj; g_pos[j] = pj;
        }
    }
    // zero 32 accumulator rows per block
    if (t < 32) {
        int idx = bb * 32 + t;
        g_accS[idx] = 0ull; g_accA[idx] = 0ull; g_accW[idx] = 0ull;
    }
}

// ---------------- K3: fused symmetric Gram GEMM + row statistics ------------
// Upper-triangular tiles (528 CTAs). Mainloop: 256 thr, 8 warps (2x4),
// warp tile 64x32, BK=64, 3-stage cp.async pipeline, fully unrolled chunk
// loop (constant stage indices), XOR-swizzled smem, ldmatrix. Fused epilogue.
extern __shared__ uint8_t dynsmem[];

__global__ __launch_bounds__(256, 2) void k_gemm_fused() {
    int tid = threadIdx.x;
    int warp = tid >> 5, lane = tid & 31;
    int g = lane >> 2, tq = lane & 3;
    int warpRow = (warp >> 2) * 64;
    int warpCol = (warp & 3) * 32;

    // triangular decode: blockIdx.x -> (by, bx) with bx >= by
    int b = blockIdx.x, by = 0;
    while (b >= 32 - by) { b -= 32 - by; ++by; }
    int bx = by + b;
    int rowBase = by * BM, colBase = bx * BN;
    bool diag = (bx == by);

    uint32_t raw = smem_u32(dynsmem);
    uint32_t base = (raw + 1023u) & ~1023u;
    uint32_t sa[NSTAGE], sb[NSTAGE];
    #pragma unroll
    for (int s = 0; s < NSTAGE; ++s) {
        sa[s] = base + s * 16384u;
        sb[s] = base + (NSTAGE + s) * 16384u;
    }
    uint8_t* ep = dynsmem + (base - raw);   // epilogue scratch (reuses stages)
    float* pR_s = reinterpret_cast<float*>(ep);            // [128]
    float* iR_s = pR_s + 128;                              // [128]
    int*   lR_s = reinterpret_cast<int*>(iR_s + 128);      // [128]
    float* pC_s = reinterpret_cast<float*>(lR_s + 128);    // [128]
    float* iC_s = pC_s + 128;                              // [128]
    int*   lC_s = reinterpret_cast<int*>(iC_s + 128);      // [128]
    float* partR = reinterpret_cast<float*>(lC_s + 128);   // [8][64][3]
    float* partC = partR + 8 * 64 * 3;                     // [8][32][3]

    float acc[4][4][4];
    #pragma unroll
    for (int a = 0; a < 4; ++a)
        #pragma unroll
        for (int c = 0; c < 4; ++c)
            #pragma unroll
            for (int k = 0; k < 4; ++k) acc[a][c][k] = 0.f;

    const char* Ub = reinterpret_cast<const char*>(g_U);  // row stride 1024B

    int arow   = (lane & 7) + ((lane >> 3) & 1) * 8;
    int achsel = lane >> 4;
    int brow   = (lane & 7) + ((lane >> 4) << 3);
    int bchsel = (lane >> 3) & 1;
    int lxor   = lane & 7;

    #define LOAD_TILES(st, ck) do {                                            \
        uint32_t _sa = sa[st], _sb = sb[st];                                   \
        _Pragma("unroll")                                                      \
        for (int _i = 0; _i < 4; ++_i) {                                       \
            int _idx = _i * 256 + tid;                                         \
            int _row = _idx >> 3, _ch = _idx & 7;                              \
            uint32_t _sw = _row * 128 + ((_ch ^ (_row & 7)) << 4);             \
            cp16(_sa + _sw, Ub + (size_t)(rowBase + _row) * 1024 + (ck) * 128 + _ch * 16); \
            cp16(_sb + _sw, Ub + (size_t)(colBase + _row) * 1024 + (ck) * 128 + _ch * 16); \
        }                                                                      \
        CP_COMMIT();                                                           \
    } while (0)

    LOAD_TILES(0, 0);
    LOAD_TILES(1, 1);

    #pragma unroll
    for (int s = 0; s < NCHUNK; ++s) {
        int st = s % NSTAGE;
        if (s < NCHUNK - 1) asm volatile("cp.async.wait_group 1;" ::: "memory");
        else                asm volatile("cp.async.wait_group 0;" ::: "memory");
        __syncthreads();
        // issue loads for s+2 into the stage vacated last iteration
        if (s + 2 < NCHUNK) {
            int st2 = (s + 2) % NSTAGE;
            LOAD_TILES(st2, s + 2);
        }

        uint32_t saSt = sa[st], sbSt = sb[st];
        #pragma unroll
        for (int kk = 0; kk < 4; ++kk) {
            uint32_t af[4][4], bf[4][2];
            #pragma unroll
            for (int mi = 0; mi < 4; ++mi) {
                uint32_t addr = saSt + (warpRow + mi * 16 + arow) * 128
                              + (((kk * 2 + achsel) ^ lxor) << 4);
                ldsm4(af[mi][0], af[mi][1], af[mi][2], af[mi][3], addr);
            }
            #pragma unroll
            for (int n2 = 0; n2 < 2; ++n2) {
                uint32_t addr = sbSt + (warpCol + n2 * 16 + brow) * 128
                              + (((kk * 2 + bchsel) ^ lxor) << 4);
                uint32_t r0, r1, r2, r3;
                ldsm4(r0, r1, r2, r3, addr);
                bf[n2 * 2][0] = r0;     bf[n2 * 2][1] = r1;
                bf[n2 * 2 + 1][0] = r2; bf[n2 * 2 + 1][1] = r3;
            }
            #pragma unroll
            for (int mi = 0; mi < 4; ++mi)
                #pragma unroll
                for (int ni = 0; ni < 4; ++ni)
                    mma16816(acc[mi][ni], af[mi], bf[ni]);
        }
    }
    #undef LOAD_TILES

    __syncthreads();   // all compute done; stage buffers reusable

    // ================= fused epilogue =================
    if (tid < 128) {
        int r = (rowBase + tid) & (N_HALF - 1);
        int c = (colBase + tid) & (N_HALF - 1);
        pR_s[tid] = g_pos[r]; iR_s[tid] = g_invs[r]; lR_s[tid] = g_lab[r];
        pC_s[tid] = g_pos[c]; iC_s[tid] = g_invs[c]; lC_s[tid] = g_lab[c];
    }
    __syncthreads();

    float rS[8], rA[8], rW[8], cS[8], cA[8], cW[8];
    #pragma unroll
    for (int i = 0; i < 8; ++i) {
        rS[i] = rA[i] = rW[i] = 0.f;
        cS[i] = cA[i] = cW[i] = 0.f;
    }

    #pragma unroll
    for (int mi = 0; mi < 4; ++mi) {
        #pragma unroll
        for (int kh = 0; kh < 2; ++kh) {
            int rl = warpRow + mi * 16 + kh * 8 + g;
            float pr = pR_s[rl], ir = iR_s[rl];
            int   lr = lR_s[rl];
            int idxR = mi * 2 + kh;
            #pragma unroll
            for (int ni = 0; ni < 4; ++ni) {
                #pragma unroll
                for (int kb = 0; kb < 2; ++kb) {
                    int cl = warpCol + ni * 8 + tq * 2 + kb;
                    float sim = acc[mi][ni][kh * 2 + kb] * TEMP_INV;
                    float eS = __expf(sim - TEMP_INV);
                    float d  = pr - pC_s[cl];
                    float wk = (lr == lC_s[cl]) ? __expf(-GAMMA * d * d) : 0.f;
                    if (diag && rl == cl) { eS = 0.f; wk = 0.f; }
                    float wc = wk * iC_s[cl];
                    int idxC = ni * 2 + kb;
                    rS[idxR] += eS; rA[idxR] += sim * wc; rW[idxR] += wc;
                    float wr = wk * ir;
                    cS[idxC] += eS; cA[idxC] += sim * wr; cW[idxC] += wr;
                }
            }
        }
    }

    // warp reductions: rows over tq (xor 1,2); cols over g (xor 4,8,16)
    #pragma unroll
    for (int i = 0; i < 8; ++i) {
        rS[i] += __shfl_xor_sync(0xffffffffu, rS[i], 1);
        rS[i] += __shfl_xor_sync(0xffffffffu, rS[i], 2);
        rA[i] += __shfl_xor_sync(0xffffffffu, rA[i], 1);
        rA[i] += __shfl_xor_sync(0xffffffffu, rA[i], 2);
        rW[i] += __shfl_xor_sync(0xffffffffu, rW[i], 1);
        rW[i] += __shfl_xor_sync(0xffffffffu, rW[i], 2);
        cS[i] += __shfl_xor_sync(0xffffffffu, cS[i], 4);
        cS[i] += __shfl_xor_sync(0xffffffffu, cS[i], 8);
        cS[i] += __shfl_xor_sync(0xffffffffu, cS[i], 16);
        cA[i] += __shfl_xor_sync(0xffffffffu, cA[i], 4);
        cA[i] += __shfl_xor_sync(0xffffffffu, cA[i], 8);
        cA[i] += __shfl_xor_sync(0xffffffffu, cA[i], 16);
        cW[i] += __shfl_xor_sync(0xffffffffu, cW[i], 4);
        cW[i] += __shfl_xor_sync(0xffffffffu, cW[i], 8);
        cW[i] += __shfl_xor_sync(0xffffffffu, cW[i], 16);
    }
    if (tq == 0) {
        #pragma unroll
        for (int i = 0; i < 8; ++i) {
            int rl = (i >> 1) * 16 + (i & 1) * 8 + g;   // 0..63 within warp
            float* p = &partR[(warp * 64 + rl) * 3];
            p[0] = rS[i]; p[1] = rA[i]; p[2] = rW[i];
        }
    }
    if (g == 0) {
        #pragma unroll
        for (int i = 0; i < 8; ++i) {
            int cl = (i >> 1) * 8 + tq * 2 + (i & 1);   // 0..31 within warp
            float* p = &partC[(warp * 32 + cl) * 3];
            p[0] = cS[i]; p[1] = cA[i]; p[2] = cW[i];
        }
    }
    __syncthreads();

    // CTA-level sums + deterministic fixed-point atomics.
    // Threads 0-127: row stats. Threads 128-255: col stats (mirror tiles).
    if (tid < 128) {
        int wb = (tid >> 6) * 4;      // rows 0-63 <- warps 0-3; 64-127 <- 4-7
        int lr2 = tid & 63;
        float S = 0.f, A = 0.f, W = 0.f;
        #pragma unroll
        for (int w = 0; w < 4; ++w) {
            const float* p = &partR[((wb + w) * 64 + lr2) * 3];
            S += p[0]; A += p[1]; W += p[2];
        }
        int grow = rowBase + tid;
        atomic_add_fx(&g_accS[grow], S);
        atomic_add_fx(&g_accA[grow], A);
        atomic_add_fx(&g_accW[grow], W);
    } else if (!diag) {
        int t2 = tid - 128;           // 0..127
        int grp = t2 >> 5, lc2 = t2 & 31;
        const float* p0 = &partC[(grp * 32 + lc2) * 3];
        const float* p1 = &partC[((grp + 4) * 32 + lc2) * 3];
        float Sc = p0[0] + p1[0];
        float Ac = p0[1] + p1[1];
        float Wc = p0[2] + p1[2];
        int gcol = colBase + t2;
        atomic_add_fx(&g_accS[gcol], Sc);
        atomic_add_fx(&g_accA[gcol], Ac);
        atomic_add_fx(&g_accW[gcol], Wc);
    }
}

// ---------------- K4: final per-row loss + deterministic reduction ----------
__global__ void k_final(float* __restrict__ out) {
    int t = threadIdx.x;  // 1024
    const float inv_scale = (float)(1.0 / FP_SCALE);
    float a = 0.f;
    #pragma unroll
    for (int q = 0; q < 4; ++q) {
        int r = t + q * 1024;
        float S = (float)(long long)g_accS[r] * inv_scale;
        float A = (float)(long long)g_accA[r] * inv_scale;
        float W = (float)(long long)g_accW[r] * inv_scale;
        float lse = TEMP_INV + logf(S);
        a += A - lse * W;
    }
    #pragma unroll
    for (int o = 16; o > 0; o >>= 1) a += __shfl_xor_sync(0xffffffffu, a, o);
    __shared__ float sred[32];
    if ((t & 31) == 0) sred[t >> 5] = a;
    __syncthreads();
    if (t == 0) {
        float tot = 0.f;
        #pragma unroll
        for (int w = 0; w < 32; ++w) tot += sred[w];
        out[0] = -tot / (float)N_HALF;
    }
}

// ---------------- launch -----------------------------------------------------
extern "C" void kernel_launch(void* const* d_in, const int* in_sizes, int n_in,
                              void* d_out, int out_size) {
    const float* z_i   = (const float*)d_in[0];
    const float* z_j   = (const float*)d_in[1];
    const int*   labs  = (const int*)d_in[2];
    const float* z_pos = (const float*)d_in[3];
    float* out = (float*)d_out;

    const int dyn_smem = 99328;   // 6 x 16KB stage buffers + 1KB align slack
    cudaFuncSetAttribute(k_gemm_fused, cudaFuncAttributeMaxDynamicSharedMemorySize,
                         dyn_smem);

    k_norm<<<NTOT, 128>>>(z_i, z_j);
    k_colscale<<<128, 256>>>(labs, z_pos);
    k_gemm_fused<<<528, 256, dyn_smem>>>();
    k_final<<<1, 1024>>>(out);
}